// round 5
// baseline (speedup 1.0000x reference)
#include <cuda_runtime.h>
#include <cstdint>

#define EDGES 200000
#define ROWSZ 400000
#define CDIM  128
#define NPAD  50048      // 391*128, padded node count

// ---------------- scratch (static device allocations) ----------------
__device__ float g_S[NPAD * CDIM];          // segment sum of x
__device__ float g_T[NPAD * CDIM];          // segment sum of pair sums
__device__ int   g_deg[NPAD];               // rows per node
__device__ float g_Z[NPAD * 256];           // [deg*S, (deg-1)*S + T]
__device__ float g_P[NPAD * 256];           // S @ Bw
__device__ float g_Q[NPAD * 256];           // Z @ Cw
__device__ float g_Y[102400000];            // pre-BN1 activations [2E, 256]
__device__ float g_A[CDIM * 256];           // W0 + Wm2
__device__ float g_Bw[CDIM * 256];          // Wm1 + Wm2
__device__ float g_Cw[256 * 256];           // Wl + Wm
__device__ float g_stat1[512];              // col sum / sumsq of Y
__device__ float g_stat2[256];              // col sum / sumsq of pre-BN2
__device__ float g_sc1[256], g_sh1[256];
__device__ float g_sc2[128], g_sh2[128];

// ---------------- weight folding ----------------
__global__ void prep_w(const float* __restrict__ w1) {
    int idx = blockIdx.x * blockDim.x + threadIdx.x;   // 65536
    int k = idx >> 8;
    int j = idx & 255;
    g_Cw[idx] = w1[(128 + k) * 256 + j] + w1[(384 + k) * 256 + j];
    if (k < 128) {
        g_A[idx]  = w1[k * 256 + j]         + w1[(512 + k) * 256 + j];
        g_Bw[idx] = w1[(384 + k) * 256 + j] + w1[(512 + k) * 256 + j];
    }
}

// ---------------- per-edge segment accumulation ----------------
__global__ void edge_accum(const float* __restrict__ x, const int* __restrict__ ei) {
    int gw   = (blockIdx.x * blockDim.x + threadIdx.x) >> 5;
    int lane = threadIdx.x & 31;
    if (gw >= EDGES) return;
    int n0 = ei[2 * gw], n1 = ei[2 * gw + 1];
    const float4* x4 = (const float4*)x;
    float4 a = x4[(size_t)(2 * gw) * 32 + lane];
    float4 b = x4[(size_t)(2 * gw) * 32 + 32 + lane];
    float4 p = make_float4(a.x + b.x, a.y + b.y, a.z + b.z, a.w + b.w);
    atomicAdd((float4*)&g_S[(size_t)n0 * CDIM + lane * 4], a);
    atomicAdd((float4*)&g_S[(size_t)n1 * CDIM + lane * 4], b);
    atomicAdd((float4*)&g_T[(size_t)n0 * CDIM + lane * 4], p);
    atomicAdd((float4*)&g_T[(size_t)n1 * CDIM + lane * 4], p);
    if (lane == 0) { atomicAdd(&g_deg[n0], 1); atomicAdd(&g_deg[n1], 1); }
}

// ---------------- build Z = [deg*S, (deg-1)*S + T] ----------------
__global__ void build_Z() {
    int idx = blockIdx.x * blockDim.x + threadIdx.x;   // NPAD*128
    int n = idx >> 7, c = idx & 127;
    float s  = g_S[idx];
    float tt = g_T[idx];
    float d  = (float)g_deg[n];
    g_Z[(size_t)n * 256 + c]       = d * s;
    g_Z[(size_t)n * 256 + 128 + c] = (d - 1.0f) * s + tt;
}

// ================= tensor-core GEMM (3xTF32) =================
__device__ __forceinline__ float tf32_rna(float x) {
    uint32_t u; asm("cvt.rna.tf32.f32 %0, %1;" : "=r"(u) : "f"(x));
    return __uint_as_float(u);
}
__device__ __forceinline__ void mma_tf32(float* d,
    uint32_t a0, uint32_t a1, uint32_t a2, uint32_t a3,
    uint32_t b0, uint32_t b1)
{
    asm volatile(
        "mma.sync.aligned.m16n8k8.row.col.f32.tf32.tf32.f32 "
        "{%0,%1,%2,%3}, {%4,%5,%6,%7}, {%8,%9}, {%0,%1,%2,%3};"
        : "+f"(d[0]), "+f"(d[1]), "+f"(d[2]), "+f"(d[3])
        : "r"(a0), "r"(a1), "r"(a2), "r"(a3), "r"(b0), "r"(b1));
}

#define AMP 264   // floats per A smem k-row (132 float2, hi/lo interleaved)
#define BNP 264
#define CSP 132

struct SmemGemm {
    union {
        struct { float a[32 * AMP]; float b[32 * BNP]; } st;   // 67584 B
        float c[128 * CSP];                                    // 67584 B
    } u;
    float ssum[128], ssq[128];
    float sc[256], sh[256];
    int snode[128], soth[128];
};

// MODE 0: Out = A@W                          (node GEMMs)
// MODE 1: Out = A@W + P[other] + Q[node], stat1   (GEMM1 -> Y)
// MODE 2: Out = relu(bn1(A))@W, stat2             (GEMM2 -> d_out)
template<int KDIM, int OUTW, int MODE>
__global__ void __launch_bounds__(256, 1)
gemm_mma(const float* __restrict__ Amat, const float* __restrict__ Wmat,
         float* __restrict__ Out, const int* __restrict__ ei)
{
    extern __shared__ __align__(16) char smraw[];
    SmemGemm* sm = (SmemGemm*)smraw;
    const int t    = threadIdx.x;
    const int lane = t & 31;
    const int w    = t >> 5;
    const int row0 = blockIdx.x * 128;
    const int col0 = blockIdx.y * 128;
    const int wm   = (w >> 2) * 64;   // warp m offset
    const int wn   = (w & 3) * 32;    // warp n offset
    const int fr   = lane >> 2;
    const int fc   = lane & 3;

    if (MODE == 1 && t < 128) { int r = row0 + t; sm->snode[t] = ei[r]; sm->soth[t] = ei[r ^ 1]; }
    if (MODE == 2)            { sm->sc[t] = g_sc1[t]; sm->sh[t] = g_sh1[t]; }
    if (t < 128)              { sm->ssum[t] = 0.0f; sm->ssq[t] = 0.0f; }
    __syncthreads();

    float acc[4][4][4];
    #pragma unroll
    for (int a = 0; a < 4; a++)
        #pragma unroll
        for (int b = 0; b < 4; b++)
            #pragma unroll
            for (int c = 0; c < 4; c++) acc[a][b][c] = 0.0f;

    float4 pa[4], pb[4];
    #pragma unroll
    for (int i = 0; i < 4; i++) {                     // prefetch stage 0
        int idx = i * 256 + t;
        pa[i] = *(const float4*)&Amat[(size_t)(row0 + (idx >> 3)) * KDIM + ((idx & 7) << 2)];
        pb[i] = *(const float4*)&Wmat[(size_t)(idx >> 5) * OUTW + col0 + ((idx & 31) << 2)];
    }

    for (int kt = 0; kt < KDIM; kt += 32) {
        // ---- store stage (split fp32 -> tf32 hi/lo) ----
        #pragma unroll
        for (int i = 0; i < 4; i++) {
            int idx = i * 256 + t; int ar = idx >> 3; int akq = idx & 7;
            float v[4] = {pa[i].x, pa[i].y, pa[i].z, pa[i].w};
            #pragma unroll
            for (int j = 0; j < 4; j++) {
                float xv = v[j];
                if (MODE == 2) {
                    int kk = kt + akq * 4 + j;
                    xv = fmaxf(fmaf(xv, sm->sc[kk], sm->sh[kk]), 0.0f);
                }
                float hi = tf32_rna(xv);
                float lo = tf32_rna(xv - hi);
                float* p = &sm->u.st.a[(akq * 4 + j) * AMP + 2 * ar];
                p[0] = hi; p[1] = lo;
            }
        }
        #pragma unroll
        for (int i = 0; i < 4; i++) {
            int idx = i * 256 + t; int bk = idx >> 5; int bnq = idx & 31;
            float h0 = tf32_rna(pb[i].x), l0 = tf32_rna(pb[i].x - h0);
            float h1 = tf32_rna(pb[i].y), l1 = tf32_rna(pb[i].y - h1);
            float h2 = tf32_rna(pb[i].z), l2 = tf32_rna(pb[i].z - h2);
            float h3 = tf32_rna(pb[i].w), l3 = tf32_rna(pb[i].w - h3);
            float* p = &sm->u.st.b[bk * BNP + 8 * bnq];
            *(float4*)p       = make_float4(h0, l0, h1, l1);
            *(float4*)(p + 4) = make_float4(h2, l2, h3, l3);
        }
        __syncthreads();

        if (kt + 32 < KDIM) {                          // prefetch next stage
            #pragma unroll
            for (int i = 0; i < 4; i++) {
                int idx = i * 256 + t;
                pa[i] = *(const float4*)&Amat[(size_t)(row0 + (idx >> 3)) * KDIM + kt + 32 + ((idx & 7) << 2)];
                pb[i] = *(const float4*)&Wmat[(size_t)(kt + 32 + (idx >> 5)) * OUTW + col0 + ((idx & 31) << 2)];
            }
        }

        // ---- compute 4 k8-steps ----
        #pragma unroll
        for (int ks = 0; ks < 4; ks++) {
            int k0 = ks * 8;
            uint32_t ah[4][4], al[4][4];
            #pragma unroll
            for (int mi = 0; mi < 4; mi++) {
                int m = wm + mi * 16 + fr;
                float2 v0 = *(float2*)&sm->u.st.a[(k0 + fc) * AMP + 2 * m];
                float2 v1 = *(float2*)&sm->u.st.a[(k0 + fc) * AMP + 2 * (m + 8)];
                float2 v2 = *(float2*)&sm->u.st.a[(k0 + fc + 4) * AMP + 2 * m];
                float2 v3 = *(float2*)&sm->u.st.a[(k0 + fc + 4) * AMP + 2 * (m + 8)];
                ah[mi][0] = __float_as_uint(v0.x); al[mi][0] = __float_as_uint(v0.y);
                ah[mi][1] = __float_as_uint(v1.x); al[mi][1] = __float_as_uint(v1.y);
                ah[mi][2] = __float_as_uint(v2.x); al[mi][2] = __float_as_uint(v2.y);
                ah[mi][3] = __float_as_uint(v3.x); al[mi][3] = __float_as_uint(v3.y);
            }
            #pragma unroll
            for (int ni = 0; ni < 4; ni++) {
                int n = wn + ni * 8 + fr;
                float2 b0 = *(float2*)&sm->u.st.b[(k0 + fc) * BNP + 2 * n];
                float2 b1 = *(float2*)&sm->u.st.b[(k0 + fc + 4) * BNP + 2 * n];
                uint32_t bh0 = __float_as_uint(b0.x), bl0 = __float_as_uint(b0.y);
                uint32_t bh1 = __float_as_uint(b1.x), bl1 = __float_as_uint(b1.y);
                #pragma unroll
                for (int mi = 0; mi < 4; mi++) {
                    mma_tf32(acc[mi][ni], ah[mi][0], ah[mi][1], ah[mi][2], ah[mi][3], bh0, bh1);
                    mma_tf32(acc[mi][ni], ah[mi][0], ah[mi][1], ah[mi][2], ah[mi][3], bl0, bl1);
                    mma_tf32(acc[mi][ni], al[mi][0], al[mi][1], al[mi][2], al[mi][3], bh0, bh1);
                }
            }
        }
        __syncthreads();
    }

    // ---- epilogue: acc -> smem tile ----
    #pragma unroll
    for (int mi = 0; mi < 4; mi++)
        #pragma unroll
        for (int ni = 0; ni < 4; ni++) {
            int r  = wm + mi * 16 + fr;
            int cb = wn + ni * 8 + fc * 2;
            *(float2*)&sm->u.c[r * CSP + cb]       = make_float2(acc[mi][ni][0], acc[mi][ni][1]);
            *(float2*)&sm->u.c[(r + 8) * CSP + cb] = make_float2(acc[mi][ni][2], acc[mi][ni][3]);
        }
    __syncthreads();

    const int c4 = (t & 31) * 4;
    const int rb = t >> 5;
    float cs[4] = {0, 0, 0, 0}, cq[4] = {0, 0, 0, 0};
    #pragma unroll
    for (int i = 0; i < 16; i++) {
        int r = rb + i * 8;
        float4 v = *(float4*)&sm->u.c[r * CSP + c4];
        if (MODE == 1) {
            int nr = sm->snode[r], orr = sm->soth[r];
            float4 p = *(const float4*)&g_P[(size_t)orr * 256 + col0 + c4];
            float4 q = *(const float4*)&g_Q[(size_t)nr  * 256 + col0 + c4];
            v.x += p.x + q.x; v.y += p.y + q.y; v.z += p.z + q.z; v.w += p.w + q.w;
        }
        if (MODE >= 1) {
            cs[0] += v.x; cq[0] += v.x * v.x;
            cs[1] += v.y; cq[1] += v.y * v.y;
            cs[2] += v.z; cq[2] += v.z * v.z;
            cs[3] += v.w; cq[3] += v.w * v.w;
        }
        *(float4*)&Out[(size_t)(row0 + r) * OUTW + col0 + c4] = v;
    }
    if (MODE >= 1) {
        #pragma unroll
        for (int j = 0; j < 4; j++) {
            atomicAdd(&sm->ssum[c4 + j], cs[j]);
            atomicAdd(&sm->ssq[c4 + j],  cq[j]);
        }
        __syncthreads();
        if (t < 128) {
            float* stat = (MODE == 1) ? g_stat1 : g_stat2;
            int half    = (MODE == 1) ? 256 : 128;
            atomicAdd(&stat[col0 + t],        sm->ssum[t]);
            atomicAdd(&stat[half + col0 + t], sm->ssq[t]);
        }
    }
}

// ---------------- BN finalize ----------------
__global__ void finalize1(const float* __restrict__ g, const float* __restrict__ b) {
    int c = threadIdx.x;   // 256
    float inv = 1.0f / (float)ROWSZ;
    float m   = g_stat1[c] * inv;
    float var = g_stat1[256 + c] * inv - m * m;
    float is  = rsqrtf(var + 1e-5f);
    g_sc1[c] = g[c] * is;
    g_sh1[c] = b[c] - m * is * g[c];
}

__global__ void finalize2(const float* __restrict__ g, const float* __restrict__ b) {
    int c = threadIdx.x;   // 128
    float inv = 1.0f / (float)ROWSZ;
    float m   = g_stat2[c] * inv;
    float var = g_stat2[128 + c] * inv - m * m;
    float is  = rsqrtf(var + 1e-5f);
    g_sc2[c] = g[c] * is;
    g_sh2[c] = b[c] - m * is * g[c];
}

// ---------------- final BN2 + ReLU in place on d_out ----------------
__global__ void bn2_relu(float* __restrict__ out) {
    int idx = blockIdx.x * blockDim.x + threadIdx.x;   // ROWSZ*32 float4s
    float4 v = ((float4*)out)[idx];
    int c = (idx & 31) * 4;
    v.x = fmaxf(fmaf(v.x, g_sc2[c + 0], g_sh2[c + 0]), 0.0f);
    v.y = fmaxf(fmaf(v.y, g_sc2[c + 1], g_sh2[c + 1]), 0.0f);
    v.z = fmaxf(fmaf(v.z, g_sc2[c + 2], g_sh2[c + 2]), 0.0f);
    v.w = fmaxf(fmaf(v.w, g_sc2[c + 3], g_sh2[c + 3]), 0.0f);
    ((float4*)out)[idx] = v;
}

extern "C" void kernel_launch(void* const* d_in, const int* in_sizes, int n_in,
                              void* d_out, int out_size)
{
    const float* x  = (const float*)d_in[0];
    const float* w1 = (const float*)d_in[1];
    const float* g1 = (const float*)d_in[2];
    const float* b1 = (const float*)d_in[3];
    const float* w2 = (const float*)d_in[4];
    const float* g2 = (const float*)d_in[5];
    const float* b2 = (const float*)d_in[6];
    const int*   ei = (const int*)d_in[7];
    float* out = (float*)d_out;

    void *pS, *pT, *pdeg, *pZ, *pP, *pQ, *pY, *pA, *pBw, *pCw, *ps1, *ps2;
    cudaGetSymbolAddress(&pS,  g_S);
    cudaGetSymbolAddress(&pT,  g_T);
    cudaGetSymbolAddress(&pdeg, g_deg);
    cudaGetSymbolAddress(&pZ,  g_Z);
    cudaGetSymbolAddress(&pP,  g_P);
    cudaGetSymbolAddress(&pQ,  g_Q);
    cudaGetSymbolAddress(&pY,  g_Y);
    cudaGetSymbolAddress(&pA,  g_A);
    cudaGetSymbolAddress(&pBw, g_Bw);
    cudaGetSymbolAddress(&pCw, g_Cw);
    cudaGetSymbolAddress(&ps1, g_stat1);
    cudaGetSymbolAddress(&ps2, g_stat2);

    const int shb = (int)sizeof(SmemGemm);
    cudaFuncSetAttribute(gemm_mma<128, 256, 0>, cudaFuncAttributeMaxDynamicSharedMemorySize, shb);
    cudaFuncSetAttribute(gemm_mma<256, 256, 0>, cudaFuncAttributeMaxDynamicSharedMemorySize, shb);
    cudaFuncSetAttribute(gemm_mma<128, 256, 1>, cudaFuncAttributeMaxDynamicSharedMemorySize, shb);
    cudaFuncSetAttribute(gemm_mma<256, 128, 2>, cudaFuncAttributeMaxDynamicSharedMemorySize, shb);

    cudaMemsetAsync(pS,   0, sizeof(g_S));
    cudaMemsetAsync(pT,   0, sizeof(g_T));
    cudaMemsetAsync(pdeg, 0, sizeof(g_deg));
    cudaMemsetAsync(ps1,  0, sizeof(g_stat1));
    cudaMemsetAsync(ps2,  0, sizeof(g_stat2));

    prep_w<<<256, 256>>>(w1);
    edge_accum<<<(EDGES + 7) / 8, 256>>>(x, ei);
    build_Z<<<NPAD * CDIM / 256, 256>>>();

    // node GEMMs: P = S@Bw, Q = Z@Cw
    gemm_mma<128, 256, 0><<<dim3(NPAD / 128, 2), 256, shb>>>((const float*)pS, (const float*)pBw, (float*)pP, nullptr);
    gemm_mma<256, 256, 0><<<dim3(NPAD / 128, 2), 256, shb>>>((const float*)pZ, (const float*)pCw, (float*)pQ, nullptr);

    // GEMM1: Y = x@A + P[other] + Q[node], stats1
    gemm_mma<128, 256, 1><<<dim3(ROWSZ / 128, 2), 256, shb>>>(x, (const float*)pA, (float*)pY, ei);
    finalize1<<<1, 256>>>(g1, b1);

    // GEMM2: d_out = relu(bn1(Y))@w2 (pre-BN2), stats2
    gemm_mma<256, 128, 2><<<dim3(ROWSZ / 128, 1), 256, shb>>>((const float*)pY, w2, out, nullptr);
    finalize2<<<1, 128>>>(g2, b2);

    bn2_relu<<<ROWSZ * 32 / 256, 256>>>(out);
}

// round 7
// speedup vs baseline: 1.9836x; 1.9836x over previous
#include <cuda_runtime.h>
#include <cuda_bf16.h>
#include <cstdint>

#define EDGES 200000
#define ROWSZ 400000
#define CDIM  128
#define NPAD  50048      // 391*128, padded node count

// ---------------- scratch (static device allocations) ----------------
__device__ float g_S[NPAD * CDIM];          // segment sum of x
__device__ float g_T[NPAD * CDIM];          // segment sum of pair sums
__device__ int   g_deg[NPAD];               // rows per node
__device__ float g_Z[NPAD * 256];           // [deg*S, (deg-1)*S + T]
__device__ float g_P[NPAD * 256];           // S @ Bw
__device__ float g_Q[NPAD * 256];           // Z @ Cw
__device__ float g_Y[102400000];            // pre-BN1 activations [2E, 256]
__device__ float g_stat1[512];              // col sum / sumsq of Y
__device__ float g_stat2[256];              // col sum / sumsq of pre-BN2
__device__ float g_sc1[256], g_sh1[256];
__device__ float g_sc2[128], g_sh2[128];

// transposed bf16 hi/lo weight arrays: layout [n][k]
__device__ __nv_bfloat16 g_At_h[256 * 128],  g_At_l[256 * 128];   // W0+Wm2
__device__ __nv_bfloat16 g_Bwt_h[256 * 128], g_Bwt_l[256 * 128];  // Wm1+Wm2
__device__ __nv_bfloat16 g_Cwt_h[256 * 256], g_Cwt_l[256 * 256];  // Wl+Wm
__device__ __nv_bfloat16 g_w2t_h[128 * 256], g_w2t_l[128 * 256];  // w2

__device__ __forceinline__ void bsplit(float x, __nv_bfloat16& h, __nv_bfloat16& l) {
    h = __float2bfloat16(x);
    l = __float2bfloat16(x - __bfloat162float(h));
}
__device__ __forceinline__ uint32_t pack2(__nv_bfloat16 a, __nv_bfloat16 b) {
    return (uint32_t)__bfloat16_as_ushort(a) | ((uint32_t)__bfloat16_as_ushort(b) << 16);
}

// ---------------- weight folding + transpose + bf16 split ----------------
__global__ void prep_w(const float* __restrict__ w1) {
    int idx = blockIdx.x * blockDim.x + threadIdx.x;   // 65536
    int k = idx >> 8;
    int j = idx & 255;
    float cw = w1[(128 + k) * 256 + j] + w1[(384 + k) * 256 + j];
    bsplit(cw, g_Cwt_h[j * 256 + k], g_Cwt_l[j * 256 + k]);
    if (k < 128) {
        float a  = w1[k * 256 + j]         + w1[(512 + k) * 256 + j];
        float bw = w1[(384 + k) * 256 + j] + w1[(512 + k) * 256 + j];
        bsplit(a,  g_At_h[j * 128 + k],  g_At_l[j * 128 + k]);
        bsplit(bw, g_Bwt_h[j * 128 + k], g_Bwt_l[j * 128 + k]);
    }
}
__global__ void prep_w2(const float* __restrict__ w2) {
    int idx = blockIdx.x * blockDim.x + threadIdx.x;   // 32768
    int k = idx >> 7;
    int j = idx & 127;
    bsplit(w2[k * 128 + j], g_w2t_h[j * 256 + k], g_w2t_l[j * 256 + k]);
}

// ---------------- per-edge segment accumulation ----------------
__global__ void edge_accum(const float* __restrict__ x, const int* __restrict__ ei) {
    int gw   = (blockIdx.x * blockDim.x + threadIdx.x) >> 5;
    int lane = threadIdx.x & 31;
    if (gw >= EDGES) return;
    int n0 = ei[2 * gw], n1 = ei[2 * gw + 1];
    const float4* x4 = (const float4*)x;
    float4 a = x4[(size_t)(2 * gw) * 32 + lane];
    float4 b = x4[(size_t)(2 * gw) * 32 + 32 + lane];
    float4 p = make_float4(a.x + b.x, a.y + b.y, a.z + b.z, a.w + b.w);
    atomicAdd((float4*)&g_S[(size_t)n0 * CDIM + lane * 4], a);
    atomicAdd((float4*)&g_S[(size_t)n1 * CDIM + lane * 4], b);
    atomicAdd((float4*)&g_T[(size_t)n0 * CDIM + lane * 4], p);
    atomicAdd((float4*)&g_T[(size_t)n1 * CDIM + lane * 4], p);
    if (lane == 0) { atomicAdd(&g_deg[n0], 1); atomicAdd(&g_deg[n1], 1); }
}

// ---------------- build Z = [deg*S, (deg-1)*S + T] ----------------
__global__ void build_Z() {
    int idx = blockIdx.x * blockDim.x + threadIdx.x;   // NPAD*128
    int n = idx >> 7, c = idx & 127;
    float s  = g_S[idx];
    float tt = g_T[idx];
    float d  = (float)g_deg[n];
    g_Z[(size_t)n * 256 + c]       = d * s;
    g_Z[(size_t)n * 256 + 128 + c] = (d - 1.0f) * s + tt;
}

// ================= tensor-core GEMM (3x BF16, m16n8k16) =================
__device__ __forceinline__ void mma_bf16(float* d,
    uint32_t a0, uint32_t a1, uint32_t a2, uint32_t a3,
    uint32_t b0, uint32_t b1)
{
    asm volatile(
        "mma.sync.aligned.m16n8k16.row.col.f32.bf16.bf16.f32 "
        "{%0,%1,%2,%3}, {%4,%5,%6,%7}, {%8,%9}, {%0,%1,%2,%3};"
        : "+f"(d[0]), "+f"(d[1]), "+f"(d[2]), "+f"(d[3])
        : "r"(a0), "r"(a1), "r"(a2), "r"(a3), "r"(b0), "r"(b1));
}

#define APAD 40    // bf16 elements per smem row (32 used, 80B stride: conflict-free)
#define CSP  132

struct SmemGemm {
    union {
        struct {
            __nv_bfloat16 ah[128 * APAD];   // A hi tile [m][k], k-chunk of 32
            __nv_bfloat16 al[128 * APAD];   // A lo tile
            __nv_bfloat16 bh[128 * APAD];   // B hi tile [n][k]
            __nv_bfloat16 bl[128 * APAD];   // B lo tile
        } st;                               // 40960 B
        float c[128 * CSP];                 // 67584 B
    } u;
    float ssum[128], ssq[128];
    float sc[256], sh[256];
    int snode[128], soth[128];
};

// MODE 0: Out = A@W                          (node GEMMs)
// MODE 1: Out = A@W + P[other] + Q[node], stat1   (GEMM1 -> Y)
// MODE 2: Out = relu(bn1(A))@W, stat2             (GEMM2 -> d_out)
template<int KDIM, int OUTW, int MODE>
__global__ void __launch_bounds__(256, 2)
gemm_bf16(const float* __restrict__ Amat,
          const __nv_bfloat16* __restrict__ Wh, const __nv_bfloat16* __restrict__ Wl,
          float* __restrict__ Out, const int* __restrict__ ei)
{
    extern __shared__ __align__(16) char smraw[];
    SmemGemm* sm = (SmemGemm*)smraw;
    const int t    = threadIdx.x;
    const int lane = t & 31;
    const int w    = t >> 5;
    const int row0 = blockIdx.x * 128;
    const int col0 = blockIdx.y * 128;
    const int wm   = (w >> 2) * 64;   // warp m offset
    const int wn   = (w & 3) * 32;    // warp n offset
    const int fr   = lane >> 2;
    const int fc   = lane & 3;

    if (MODE == 1 && t < 128) { int r = row0 + t; sm->snode[t] = ei[r]; sm->soth[t] = ei[r ^ 1]; }
    if (MODE == 2)            { sm->sc[t] = g_sc1[t]; sm->sh[t] = g_sh1[t]; }
    if (t < 128)              { sm->ssum[t] = 0.0f; sm->ssq[t] = 0.0f; }
    __syncthreads();

    float acc[4][4][4];
    #pragma unroll
    for (int a = 0; a < 4; a++)
        #pragma unroll
        for (int b = 0; b < 4; b++)
            #pragma unroll
            for (int c = 0; c < 4; c++) acc[a][b][c] = 0.0f;

    // prefetch registers: A fp32 (4 float4), B bf16 hi/lo (2x uint4 each = 16 bf16)
    const int am = t >> 3;           // 0..31 base row (4 rows per i, stride 32)
    const int akq = t & 7;           // float4 within 32-k
    const int bn = t >> 1;           // 0..127 n-row
    const int bseg = (t & 1) * 16;   // element offset of this thread's 16-bf16 half
    float4 pa[4];
    uint4 pbh0, pbh1, pbl0, pbl1;
    #pragma unroll
    for (int i = 0; i < 4; i++)
        pa[i] = *(const float4*)&Amat[(size_t)(row0 + am + i * 32) * KDIM + (akq << 2)];
    pbh0 = *(const uint4*)&Wh[(size_t)(col0 + bn) * KDIM + bseg];
    pbh1 = *(const uint4*)&Wh[(size_t)(col0 + bn) * KDIM + bseg + 8];
    pbl0 = *(const uint4*)&Wl[(size_t)(col0 + bn) * KDIM + bseg];
    pbl1 = *(const uint4*)&Wl[(size_t)(col0 + bn) * KDIM + bseg + 8];

    for (int kt = 0; kt < KDIM; kt += 32) {
        // ---- store stage: fp32 -> bf16 hi/lo split ----
        #pragma unroll
        for (int i = 0; i < 4; i++) {
            int m = am + i * 32;
            float v[4] = {pa[i].x, pa[i].y, pa[i].z, pa[i].w};
            __nv_bfloat16 h[4], l[4];
            #pragma unroll
            for (int j = 0; j < 4; j++) {
                float xv = v[j];
                if (MODE == 2) {
                    int kk = kt + akq * 4 + j;
                    xv = fmaxf(fmaf(xv, sm->sc[kk], sm->sh[kk]), 0.0f);
                }
                bsplit(xv, h[j], l[j]);
            }
            uint2 hp = make_uint2(pack2(h[0], h[1]), pack2(h[2], h[3]));
            uint2 lp = make_uint2(pack2(l[0], l[1]), pack2(l[2], l[3]));
            *(uint2*)&sm->u.st.ah[m * APAD + akq * 4] = hp;
            *(uint2*)&sm->u.st.al[m * APAD + akq * 4] = lp;
        }
        *(uint4*)&sm->u.st.bh[bn * APAD + bseg]     = pbh0;
        *(uint4*)&sm->u.st.bh[bn * APAD + bseg + 8] = pbh1;
        *(uint4*)&sm->u.st.bl[bn * APAD + bseg]     = pbl0;
        *(uint4*)&sm->u.st.bl[bn * APAD + bseg + 8] = pbl1;
        __syncthreads();

        if (kt + 32 < KDIM) {   // prefetch next stage
            #pragma unroll
            for (int i = 0; i < 4; i++)
                pa[i] = *(const float4*)&Amat[(size_t)(row0 + am + i * 32) * KDIM + kt + 32 + (akq << 2)];
            pbh0 = *(const uint4*)&Wh[(size_t)(col0 + bn) * KDIM + kt + 32 + bseg];
            pbh1 = *(const uint4*)&Wh[(size_t)(col0 + bn) * KDIM + kt + 32 + bseg + 8];
            pbl0 = *(const uint4*)&Wl[(size_t)(col0 + bn) * KDIM + kt + 32 + bseg];
            pbl1 = *(const uint4*)&Wl[(size_t)(col0 + bn) * KDIM + kt + 32 + bseg + 8];
        }

        // ---- compute: 2 k16 steps ----
        #pragma unroll
        for (int ks = 0; ks < 2; ks++) {
            const int k0 = ks * 16 + 2 * fc;
            uint32_t ah[4][4], alr[4][4];
            #pragma unroll
            for (int mi = 0; mi < 4; mi++) {
                int base = (wm + mi * 16 + fr) * APAD + k0;
                ah[mi][0]  = *(const uint32_t*)&sm->u.st.ah[base];
                ah[mi][1]  = *(const uint32_t*)&sm->u.st.ah[base + 8 * APAD];
                ah[mi][2]  = *(const uint32_t*)&sm->u.st.ah[base + 8];
                ah[mi][3]  = *(const uint32_t*)&sm->u.st.ah[base + 8 * APAD + 8];
                alr[mi][0] = *(const uint32_t*)&sm->u.st.al[base];
                alr[mi][1] = *(const uint32_t*)&sm->u.st.al[base + 8 * APAD];
                alr[mi][2] = *(const uint32_t*)&sm->u.st.al[base + 8];
                alr[mi][3] = *(const uint32_t*)&sm->u.st.al[base + 8 * APAD + 8];
            }
            #pragma unroll
            for (int ni = 0; ni < 4; ni++) {
                int nb = (wn + ni * 8 + fr) * APAD + k0;
                uint32_t bh0 = *(const uint32_t*)&sm->u.st.bh[nb];
                uint32_t bh1 = *(const uint32_t*)&sm->u.st.bh[nb + 8];
                uint32_t bl0 = *(const uint32_t*)&sm->u.st.bl[nb];
                uint32_t bl1 = *(const uint32_t*)&sm->u.st.bl[nb + 8];
                #pragma unroll
                for (int mi = 0; mi < 4; mi++) {
                    mma_bf16(acc[mi][ni], ah[mi][0], ah[mi][1], ah[mi][2], ah[mi][3], bh0, bh1);
                    mma_bf16(acc[mi][ni], ah[mi][0], ah[mi][1], ah[mi][2], ah[mi][3], bl0, bl1);
                    mma_bf16(acc[mi][ni], alr[mi][0], alr[mi][1], alr[mi][2], alr[mi][3], bh0, bh1);
                }
            }
        }
        __syncthreads();
    }

    // ---- epilogue: acc -> smem tile ----
    #pragma unroll
    for (int mi = 0; mi < 4; mi++)
        #pragma unroll
        for (int ni = 0; ni < 4; ni++) {
            int r  = wm + mi * 16 + fr;
            int cb = wn + ni * 8 + fc * 2;
            *(float2*)&sm->u.c[r * CSP + cb]       = make_float2(acc[mi][ni][0], acc[mi][ni][1]);
            *(float2*)&sm->u.c[(r + 8) * CSP + cb] = make_float2(acc[mi][ni][2], acc[mi][ni][3]);
        }
    __syncthreads();

    const int c4 = (t & 31) * 4;
    const int rb = t >> 5;
    float cs[4] = {0, 0, 0, 0}, cq[4] = {0, 0, 0, 0};
    #pragma unroll
    for (int i = 0; i < 16; i++) {
        int r = rb + i * 8;
        float4 v = *(float4*)&sm->u.c[r * CSP + c4];
        if (MODE == 1) {
            int nr = sm->snode[r], orr = sm->soth[r];
            float4 p = *(const float4*)&g_P[(size_t)orr * 256 + col0 + c4];
            float4 q = *(const float4*)&g_Q[(size_t)nr  * 256 + col0 + c4];
            v.x += p.x + q.x; v.y += p.y + q.y; v.z += p.z + q.z; v.w += p.w + q.w;
        }
        if (MODE >= 1) {
            cs[0] += v.x; cq[0] += v.x * v.x;
            cs[1] += v.y; cq[1] += v.y * v.y;
            cs[2] += v.z; cq[2] += v.z * v.z;
            cs[3] += v.w; cq[3] += v.w * v.w;
        }
        *(float4*)&Out[(size_t)(row0 + r) * OUTW + col0 + c4] = v;
    }
    if (MODE >= 1) {
        #pragma unroll
        for (int j = 0; j < 4; j++) {
            atomicAdd(&sm->ssum[c4 + j], cs[j]);
            atomicAdd(&sm->ssq[c4 + j],  cq[j]);
        }
        __syncthreads();
        if (t < 128) {
            float* stat = (MODE == 1) ? g_stat1 : g_stat2;
            int half    = (MODE == 1) ? 256 : 128;
            atomicAdd(&stat[col0 + t],        sm->ssum[t]);
            atomicAdd(&stat[half + col0 + t], sm->ssq[t]);
        }
    }
}

// ---------------- BN finalize ----------------
__global__ void finalize1(const float* __restrict__ g, const float* __restrict__ b) {
    int c = threadIdx.x;   // 256
    float inv = 1.0f / (float)ROWSZ;
    float m   = g_stat1[c] * inv;
    float var = g_stat1[256 + c] * inv - m * m;
    float is  = rsqrtf(var + 1e-5f);
    g_sc1[c] = g[c] * is;
    g_sh1[c] = b[c] - m * is * g[c];
}

__global__ void finalize2(const float* __restrict__ g, const float* __restrict__ b) {
    int c = threadIdx.x;   // 128
    float inv = 1.0f / (float)ROWSZ;
    float m   = g_stat2[c] * inv;
    float var = g_stat2[128 + c] * inv - m * m;
    float is  = rsqrtf(var + 1e-5f);
    g_sc2[c] = g[c] * is;
    g_sh2[c] = b[c] - m * is * g[c];
}

// ---------------- final BN2 + ReLU in place on d_out ----------------
__global__ void bn2_relu(float* __restrict__ out) {
    int idx = blockIdx.x * blockDim.x + threadIdx.x;   // ROWSZ*32 float4s
    float4 v = ((float4*)out)[idx];
    int c = (idx & 31) * 4;
    v.x = fmaxf(fmaf(v.x, g_sc2[c + 0], g_sh2[c + 0]), 0.0f);
    v.y = fmaxf(fmaf(v.y, g_sc2[c + 1], g_sh2[c + 1]), 0.0f);
    v.z = fmaxf(fmaf(v.z, g_sc2[c + 2], g_sh2[c + 2]), 0.0f);
    v.w = fmaxf(fmaf(v.w, g_sc2[c + 3], g_sh2[c + 3]), 0.0f);
    ((float4*)out)[idx] = v;
}

extern "C" void kernel_launch(void* const* d_in, const int* in_sizes, int n_in,
                              void* d_out, int out_size)
{
    const float* x  = (const float*)d_in[0];
    const float* w1 = (const float*)d_in[1];
    const float* g1 = (const float*)d_in[2];
    const float* b1 = (const float*)d_in[3];
    const float* w2 = (const float*)d_in[4];
    const float* g2 = (const float*)d_in[5];
    const float* b2 = (const float*)d_in[6];
    const int*   ei = (const int*)d_in[7];
    float* out = (float*)d_out;

    void *pS, *pT, *pdeg, *pZ, *pP, *pQ, *pY, *ps1, *ps2;
    void *pAth, *pAtl, *pBwth, *pBwtl, *pCwth, *pCwtl, *pw2h, *pw2l;
    cudaGetSymbolAddress(&pS,   g_S);
    cudaGetSymbolAddress(&pT,   g_T);
    cudaGetSymbolAddress(&pdeg, g_deg);
    cudaGetSymbolAddress(&pZ,   g_Z);
    cudaGetSymbolAddress(&pP,   g_P);
    cudaGetSymbolAddress(&pQ,   g_Q);
    cudaGetSymbolAddress(&pY,   g_Y);
    cudaGetSymbolAddress(&ps1,  g_stat1);
    cudaGetSymbolAddress(&ps2,  g_stat2);
    cudaGetSymbolAddress(&pAth,  g_At_h);  cudaGetSymbolAddress(&pAtl,  g_At_l);
    cudaGetSymbolAddress(&pBwth, g_Bwt_h); cudaGetSymbolAddress(&pBwtl, g_Bwt_l);
    cudaGetSymbolAddress(&pCwth, g_Cwt_h); cudaGetSymbolAddress(&pCwtl, g_Cwt_l);
    cudaGetSymbolAddress(&pw2h,  g_w2t_h); cudaGetSymbolAddress(&pw2l,  g_w2t_l);

    const int shb = (int)sizeof(SmemGemm);
    cudaFuncSetAttribute(gemm_bf16<128, 256, 0>, cudaFuncAttributeMaxDynamicSharedMemorySize, shb);
    cudaFuncSetAttribute(gemm_bf16<256, 256, 0>, cudaFuncAttributeMaxDynamicSharedMemorySize, shb);
    cudaFuncSetAttribute(gemm_bf16<128, 256, 1>, cudaFuncAttributeMaxDynamicSharedMemorySize, shb);
    cudaFuncSetAttribute(gemm_bf16<256, 128, 2>, cudaFuncAttributeMaxDynamicSharedMemorySize, shb);

    cudaMemsetAsync(pS,   0, sizeof(g_S));
    cudaMemsetAsync(pT,   0, sizeof(g_T));
    cudaMemsetAsync(pdeg, 0, sizeof(g_deg));
    cudaMemsetAsync(ps1,  0, sizeof(g_stat1));
    cudaMemsetAsync(ps2,  0, sizeof(g_stat2));

    prep_w<<<256, 256>>>(w1);
    prep_w2<<<128, 256>>>(w2);
    edge_accum<<<(EDGES + 7) / 8, 256>>>(x, ei);
    build_Z<<<NPAD * CDIM / 256, 256>>>();

    // node GEMMs: P = S@Bw, Q = Z@Cw
    gemm_bf16<128, 256, 0><<<dim3(NPAD / 128, 2), 256, shb>>>(
        (const float*)pS, (const __nv_bfloat16*)pBwth, (const __nv_bfloat16*)pBwtl, (float*)pP, nullptr);
    gemm_bf16<256, 256, 0><<<dim3(NPAD / 128, 2), 256, shb>>>(
        (const float*)pZ, (const __nv_bfloat16*)pCwth, (const __nv_bfloat16*)pCwtl, (float*)pQ, nullptr);

    // GEMM1: Y = x@A + P[other] + Q[node], stats1
    gemm_bf16<128, 256, 1><<<dim3(ROWSZ / 128, 2), 256, shb>>>(
        x, (const __nv_bfloat16*)pAth, (const __nv_bfloat16*)pAtl, (float*)pY, ei);
    finalize1<<<1, 256>>>(g1, b1);

    // GEMM2: d_out = relu(bn1(Y))@w2 (pre-BN2), stats2
    gemm_bf16<256, 128, 2><<<dim3(ROWSZ / 128, 1), 256, shb>>>(
        (const float*)pY, (const __nv_bfloat16*)pw2h, (const __nv_bfloat16*)pw2l, out, nullptr);
    finalize2<<<1, 128>>>(g2, b2);

    bn2_relu<<<ROWSZ * 32 / 256, 256>>>(out);
}

// round 8
// speedup vs baseline: 2.0981x; 1.0577x over previous
#include <cuda_runtime.h>
#include <cuda_bf16.h>
#include <cstdint>

#define EDGES 200000
#define ROWSZ 400000
#define CDIM  128
#define NPAD  50048      // 391*128, padded node count

// ---------------- scratch (static device allocations) ----------------
__device__ float g_S[NPAD * CDIM];
__device__ float g_T[NPAD * CDIM];
__device__ int   g_deg[NPAD];
__device__ float g_P[NPAD * 256];
__device__ float g_Q[NPAD * 256];
__device__ float g_Y[102400000];            // pre-BN1 activations [2E, 256]
__device__ float g_stat1[512];
__device__ float g_stat2[256];
__device__ float g_sc1[256], g_sh1[256];
__device__ float g_sc2[128], g_sh2[128];

// pre-split bf16 activations
__device__ __nv_bfloat16 g_Xh[(size_t)ROWSZ * CDIM], g_Xl[(size_t)ROWSZ * CDIM];
__device__ __nv_bfloat16 g_Sh[NPAD * CDIM], g_Sl[NPAD * CDIM];
__device__ __nv_bfloat16 g_Zh[NPAD * 256],  g_Zl[NPAD * 256];

// transposed bf16 hi/lo weights: layout [n][k]
__device__ __nv_bfloat16 g_At_h[256 * 128],  g_At_l[256 * 128];
__device__ __nv_bfloat16 g_Bwt_h[256 * 128], g_Bwt_l[256 * 128];
__device__ __nv_bfloat16 g_Cwt_h[256 * 256], g_Cwt_l[256 * 256];
__device__ __nv_bfloat16 g_w2t_h[128 * 256], g_w2t_l[128 * 256];

__device__ __forceinline__ void bsplit(float x, __nv_bfloat16& h, __nv_bfloat16& l) {
    h = __float2bfloat16(x);
    l = __float2bfloat16(x - __bfloat162float(h));
}
__device__ __forceinline__ uint32_t pack2(__nv_bfloat16 a, __nv_bfloat16 b) {
    return (uint32_t)__bfloat16_as_ushort(a) | ((uint32_t)__bfloat16_as_ushort(b) << 16);
}

// ---------------- weight folding + transpose + bf16 split ----------------
__global__ void prep_w(const float* __restrict__ w1) {
    int idx = blockIdx.x * blockDim.x + threadIdx.x;   // 65536
    int k = idx >> 8, j = idx & 255;
    float cw = w1[(128 + k) * 256 + j] + w1[(384 + k) * 256 + j];
    bsplit(cw, g_Cwt_h[j * 256 + k], g_Cwt_l[j * 256 + k]);
    if (k < 128) {
        float a  = w1[k * 256 + j]         + w1[(512 + k) * 256 + j];
        float bw = w1[(384 + k) * 256 + j] + w1[(512 + k) * 256 + j];
        bsplit(a,  g_At_h[j * 128 + k],  g_At_l[j * 128 + k]);
        bsplit(bw, g_Bwt_h[j * 128 + k], g_Bwt_l[j * 128 + k]);
    }
}
__global__ void prep_w2(const float* __restrict__ w2) {
    int idx = blockIdx.x * blockDim.x + threadIdx.x;   // 32768
    int k = idx >> 7, j = idx & 127;
    bsplit(w2[k * 128 + j], g_w2t_h[j * 256 + k], g_w2t_l[j * 256 + k]);
}

// ---------------- split X into bf16 hi/lo ----------------
__global__ void split_x(const float* __restrict__ x) {
    size_t i = (size_t)blockIdx.x * blockDim.x + threadIdx.x;   // ROWSZ*CDIM/4
    float4 v = ((const float4*)x)[i];
    __nv_bfloat16 h0,h1,h2,h3,l0,l1,l2,l3;
    bsplit(v.x,h0,l0); bsplit(v.y,h1,l1); bsplit(v.z,h2,l2); bsplit(v.w,h3,l3);
    ((uint2*)g_Xh)[i] = make_uint2(pack2(h0,h1), pack2(h2,h3));
    ((uint2*)g_Xl)[i] = make_uint2(pack2(l0,l1), pack2(l2,l3));
}

// ---------------- per-edge segment accumulation ----------------
__global__ void edge_accum(const float* __restrict__ x, const int* __restrict__ ei) {
    int gw   = (blockIdx.x * blockDim.x + threadIdx.x) >> 5;
    int lane = threadIdx.x & 31;
    if (gw >= EDGES) return;
    int n0 = ei[2 * gw], n1 = ei[2 * gw + 1];
    const float4* x4 = (const float4*)x;
    float4 a = x4[(size_t)(2 * gw) * 32 + lane];
    float4 b = x4[(size_t)(2 * gw) * 32 + 32 + lane];
    float4 p = make_float4(a.x + b.x, a.y + b.y, a.z + b.z, a.w + b.w);
    atomicAdd((float4*)&g_S[(size_t)n0 * CDIM + lane * 4], a);
    atomicAdd((float4*)&g_S[(size_t)n1 * CDIM + lane * 4], b);
    atomicAdd((float4*)&g_T[(size_t)n0 * CDIM + lane * 4], p);
    atomicAdd((float4*)&g_T[(size_t)n1 * CDIM + lane * 4], p);
    if (lane == 0) { atomicAdd(&g_deg[n0], 1); atomicAdd(&g_deg[n1], 1); }
}

// ---------------- build S/Z splits ----------------
__global__ void build_Z() {
    int idx = blockIdx.x * blockDim.x + threadIdx.x;   // NPAD*128
    int n = idx >> 7, c = idx & 127;
    float s  = g_S[idx];
    float tt = g_T[idx];
    float d  = (float)g_deg[n];
    bsplit(s, g_Sh[idx], g_Sl[idx]);
    float z1 = d * s;
    float z2 = (d - 1.0f) * s + tt;
    bsplit(z1, g_Zh[n * 256 + c],       g_Zl[n * 256 + c]);
    bsplit(z2, g_Zh[n * 256 + 128 + c], g_Zl[n * 256 + 128 + c]);
}

// ================= tensor-core GEMM (3x BF16, ldmatrix + cp.async) ===========
__device__ __forceinline__ void mma_bf16(float* d,
    uint32_t a0, uint32_t a1, uint32_t a2, uint32_t a3, uint32_t b0, uint32_t b1)
{
    asm volatile(
        "mma.sync.aligned.m16n8k16.row.col.f32.bf16.bf16.f32 "
        "{%0,%1,%2,%3}, {%4,%5,%6,%7}, {%8,%9}, {%0,%1,%2,%3};"
        : "+f"(d[0]), "+f"(d[1]), "+f"(d[2]), "+f"(d[3])
        : "r"(a0), "r"(a1), "r"(a2), "r"(a3), "r"(b0), "r"(b1));
}
__device__ __forceinline__ void ldsm4(uint32_t& r0, uint32_t& r1, uint32_t& r2, uint32_t& r3,
                                      uint32_t addr)
{
    asm volatile("ldmatrix.sync.aligned.m8n8.x4.shared.b16 {%0,%1,%2,%3}, [%4];"
        : "=r"(r0), "=r"(r1), "=r"(r2), "=r"(r3) : "r"(addr));
}
__device__ __forceinline__ void cpa16(uint32_t dst, const void* src) {
    asm volatile("cp.async.cg.shared.global [%0], [%1], 16;" :: "r"(dst), "l"(src));
}
#define CP_COMMIT() asm volatile("cp.async.commit_group;" ::: "memory")
#define CP_WAIT0()  asm volatile("cp.async.wait_group 0;"  ::: "memory")

#define APAD 40    // bf16 per smem row (32 used, 80B stride: LDSM conflict-free)
#define CSP  132
#define KC   32
// stage byte layout: ah 0, al 10240, bh 20480, bl 30720; stage size 40960
#define STG  40960

struct SmemGemm {
    union {
        __nv_bfloat16 st[2 * STG / 2];      // 2 staging buffers
        float c[128 * CSP];                 // epilogue tile (67584 B)
    } u;
    float ssum[128], ssq[128];
    float sc[256], sh[256];
    int snode[128], soth[128];
};

// MODE 0: Out = A@W (A = pre-split bf16)          (node GEMMs)
// MODE 1: Out = A@W + P[other] + Q[node], stat1   (GEMM1 -> Y)
// MODE 2: Out = relu(bn1(Afp))@W, stat2           (GEMM2 -> d_out)
template<int KDIM, int OUTW, int MODE>
__global__ void __launch_bounds__(256, 2)
gemm_bf16(const __nv_bfloat16* __restrict__ Ah, const __nv_bfloat16* __restrict__ Al,
          const float* __restrict__ Afp,
          const __nv_bfloat16* __restrict__ Wh, const __nv_bfloat16* __restrict__ Wl,
          float* __restrict__ Out, const int* __restrict__ ei)
{
    extern __shared__ __align__(16) char smraw[];
    SmemGemm* sm = (SmemGemm*)smraw;
    const int t    = threadIdx.x;
    const int lane = t & 31;
    const int w    = t >> 5;
    const int col0 = blockIdx.x * 128;      // column block FAST -> L2 reuse of A
    const int row0 = blockIdx.y * 128;
    const int wm   = (w >> 2) * 64;
    const int wn   = (w & 3) * 32;
    const int fr   = lane >> 2;
    const int fc   = lane & 3;
    const uint32_t sb = (uint32_t)__cvta_generic_to_shared(smraw);

    if (MODE == 1 && t < 128) { int r = row0 + t; sm->snode[t] = ei[r]; sm->soth[t] = ei[r ^ 1]; }
    if (MODE == 2)            { sm->sc[t] = g_sc1[t]; sm->sh[t] = g_sh1[t]; }
    if (t < 128)              { sm->ssum[t] = 0.0f; sm->ssq[t] = 0.0f; }
    __syncthreads();     // sc/sh visible before prologue conversion

    float acc[4][4][4];
    #pragma unroll
    for (int a = 0; a < 4; a++)
        #pragma unroll
        for (int b = 0; b < 4; b++)
            #pragma unroll
            for (int c = 0; c < 4; c++) acc[a][b][c] = 0.0f;

    // MODE2 register-staged A
    const int am = t >> 3, akq = t & 7;
    float4 pa[4];

    // cp.async chunk mapping: 512 16B-chunks per 8KB array, 2 per thread
    #define ISSUE(s, kt) do {                                                        \
        int _b = (s) * STG;                                                          \
        _Pragma("unroll")                                                            \
        for (int _i = 0; _i < 2; _i++) {                                             \
            int _c = t * 2 + _i, _row = _c >> 2, _ko = (_c & 3) * 8;                 \
            uint32_t _so = (uint32_t)((_row * APAD + _ko) * 2);                      \
            if (MODE != 2) {                                                         \
                cpa16(sb + _b + _so,         Ah + (size_t)(row0 + _row) * KDIM + (kt) + _ko); \
                cpa16(sb + _b + 10240 + _so, Al + (size_t)(row0 + _row) * KDIM + (kt) + _ko); \
            }                                                                        \
            cpa16(sb + _b + 20480 + _so, Wh + (size_t)(col0 + _row) * KDIM + (kt) + _ko); \
            cpa16(sb + _b + 30720 + _so, Wl + (size_t)(col0 + _row) * KDIM + (kt) + _ko); \
        }                                                                            \
    } while (0)

    #define LDREGS(kt) do {                                                          \
        _Pragma("unroll")                                                            \
        for (int _i = 0; _i < 4; _i++)                                               \
            pa[_i] = *(const float4*)&Afp[(size_t)(row0 + am + _i * 32) * KDIM + (kt) + akq * 4]; \
    } while (0)

    #define STSA(s, kt) do {                                                         \
        __nv_bfloat16* _ah = (__nv_bfloat16*)(smraw + (s) * STG);                    \
        __nv_bfloat16* _al = (__nv_bfloat16*)(smraw + (s) * STG + 10240);            \
        _Pragma("unroll")                                                            \
        for (int _i = 0; _i < 4; _i++) {                                             \
            int _m = am + _i * 32;                                                   \
            float _v[4] = {pa[_i].x, pa[_i].y, pa[_i].z, pa[_i].w};                  \
            __nv_bfloat16 _h[4], _l[4];                                              \
            _Pragma("unroll")                                                        \
            for (int _j = 0; _j < 4; _j++) {                                         \
                int _kk = (kt) + akq * 4 + _j;                                       \
                float _xv = fmaxf(fmaf(_v[_j], sm->sc[_kk], sm->sh[_kk]), 0.0f);     \
                bsplit(_xv, _h[_j], _l[_j]);                                         \
            }                                                                        \
            *(uint2*)&_ah[_m * APAD + akq * 4] = make_uint2(pack2(_h[0],_h[1]), pack2(_h[2],_h[3])); \
            *(uint2*)&_al[_m * APAD + akq * 4] = make_uint2(pack2(_l[0],_l[1]), pack2(_l[2],_l[3])); \
        }                                                                            \
    } while (0)

    // prologue
    ISSUE(0, 0); CP_COMMIT();
    if (MODE == 2) { LDREGS(0); STSA(0, 0); }

    const int g  = lane >> 3, rr = lane & 7;
    const int arow = wm + (g & 1) * 8 + rr;
    const int brow = wn + (g & 1) * 8 + rr;
    const int kco  = (g >> 1) * 8;

    for (int it = 0, kt = 0; kt < KDIM; kt += KC, it ^= 1) {
        CP_WAIT0();
        __syncthreads();
        const bool more = (kt + KC < KDIM);
        if (more) {
            ISSUE(it ^ 1, kt + KC); CP_COMMIT();
            if (MODE == 2) LDREGS(kt + KC);
        }
        // ---- compute stage it ----
        {
            const uint32_t abh = sb + it * STG, abl = abh + 10240;
            const uint32_t bbh = abh + 20480,   bbl = abh + 30720;
            #pragma unroll
            for (int ks = 0; ks < 2; ks++) {
                const int k0 = ks * 16;
                uint32_t fah[4][4], fal[4][4];
                #pragma unroll
                for (int mi = 0; mi < 4; mi++) {
                    uint32_t off = (uint32_t)(((arow + mi * 16) * APAD + k0 + kco) * 2);
                    ldsm4(fah[mi][0], fah[mi][1], fah[mi][2], fah[mi][3], abh + off);
                    ldsm4(fal[mi][0], fal[mi][1], fal[mi][2], fal[mi][3], abl + off);
                }
                #pragma unroll
                for (int pi = 0; pi < 2; pi++) {
                    uint32_t off = (uint32_t)(((brow + pi * 16) * APAD + k0 + kco) * 2);
                    uint32_t h0, h1, h2, h3, l0, l1, l2, l3;
                    ldsm4(h0, h1, h2, h3, bbh + off);  // b0(ni), b0(ni+1), b1(ni), b1(ni+1)
                    ldsm4(l0, l1, l2, l3, bbl + off);
                    #pragma unroll
                    for (int q = 0; q < 2; q++) {
                        const int ni = pi * 2 + q;
                        const uint32_t B0h = q ? h1 : h0, B1h = q ? h3 : h2;
                        const uint32_t B0l = q ? l1 : l0, B1l = q ? l3 : l2;
                        #pragma unroll
                        for (int mi = 0; mi < 4; mi++) {
                            mma_bf16(acc[mi][ni], fah[mi][0], fah[mi][1], fah[mi][2], fah[mi][3], B0h, B1h);
                            mma_bf16(acc[mi][ni], fah[mi][0], fah[mi][1], fah[mi][2], fah[mi][3], B0l, B1l);
                            mma_bf16(acc[mi][ni], fal[mi][0], fal[mi][1], fal[mi][2], fal[mi][3], B0h, B1h);
                        }
                    }
                }
            }
        }
        if (MODE == 2 && more) STSA(it ^ 1, kt + KC);
    }
    __syncthreads();   // staging dead; reuse union as epilogue tile

    // ---- epilogue: acc -> smem tile ----
    #pragma unroll
    for (int mi = 0; mi < 4; mi++)
        #pragma unroll
        for (int ni = 0; ni < 4; ni++) {
            int r  = wm + mi * 16 + fr;
            int cb = wn + ni * 8 + fc * 2;
            *(float2*)&sm->u.c[r * CSP + cb]       = make_float2(acc[mi][ni][0], acc[mi][ni][1]);
            *(float2*)&sm->u.c[(r + 8) * CSP + cb] = make_float2(acc[mi][ni][2], acc[mi][ni][3]);
        }
    __syncthreads();

    const int c4 = (t & 31) * 4;
    const int rb = t >> 5;
    float cs[4] = {0, 0, 0, 0}, cq[4] = {0, 0, 0, 0};
    #pragma unroll
    for (int i = 0; i < 16; i++) {
        int r = rb + i * 8;
        float4 v = *(float4*)&sm->u.c[r * CSP + c4];
        if (MODE == 1) {
            int nr = sm->snode[r], orr = sm->soth[r];
            float4 p = *(const float4*)&g_P[(size_t)orr * 256 + col0 + c4];
            float4 q = *(const float4*)&g_Q[(size_t)nr  * 256 + col0 + c4];
            v.x += p.x + q.x; v.y += p.y + q.y; v.z += p.z + q.z; v.w += p.w + q.w;
        }
        if (MODE >= 1) {
            cs[0] += v.x; cq[0] += v.x * v.x;
            cs[1] += v.y; cq[1] += v.y * v.y;
            cs[2] += v.z; cq[2] += v.z * v.z;
            cs[3] += v.w; cq[3] += v.w * v.w;
        }
        *(float4*)&Out[(size_t)(row0 + r) * OUTW + col0 + c4] = v;
    }
    if (MODE >= 1) {
        #pragma unroll
        for (int j = 0; j < 4; j++) {
            atomicAdd(&sm->ssum[c4 + j], cs[j]);
            atomicAdd(&sm->ssq[c4 + j],  cq[j]);
        }
        __syncthreads();
        if (t < 128) {
            float* stat = (MODE == 1) ? g_stat1 : g_stat2;
            int half    = (MODE == 1) ? 256 : 128;
            atomicAdd(&stat[col0 + t],        sm->ssum[t]);
            atomicAdd(&stat[half + col0 + t], sm->ssq[t]);
        }
    }
    #undef ISSUE
    #undef LDREGS
    #undef STSA
}

// ---------------- BN finalize ----------------
__global__ void finalize1(const float* __restrict__ g, const float* __restrict__ b) {
    int c = threadIdx.x;   // 256
    float inv = 1.0f / (float)ROWSZ;
    float m   = g_stat1[c] * inv;
    float var = g_stat1[256 + c] * inv - m * m;
    float is  = rsqrtf(var + 1e-5f);
    g_sc1[c] = g[c] * is;
    g_sh1[c] = b[c] - m * is * g[c];
}
__global__ void finalize2(const float* __restrict__ g, const float* __restrict__ b) {
    int c = threadIdx.x;   // 128
    float inv = 1.0f / (float)ROWSZ;
    float m   = g_stat2[c] * inv;
    float var = g_stat2[128 + c] * inv - m * m;
    float is  = rsqrtf(var + 1e-5f);
    g_sc2[c] = g[c] * is;
    g_sh2[c] = b[c] - m * is * g[c];
}

// ---------------- final BN2 + ReLU in place on d_out ----------------
__global__ void bn2_relu(float* __restrict__ out) {
    int idx = blockIdx.x * blockDim.x + threadIdx.x;
    float4 v = ((float4*)out)[idx];
    int c = (idx & 31) * 4;
    v.x = fmaxf(fmaf(v.x, g_sc2[c + 0], g_sh2[c + 0]), 0.0f);
    v.y = fmaxf(fmaf(v.y, g_sc2[c + 1], g_sh2[c + 1]), 0.0f);
    v.z = fmaxf(fmaf(v.z, g_sc2[c + 2], g_sh2[c + 2]), 0.0f);
    v.w = fmaxf(fmaf(v.w, g_sc2[c + 3], g_sh2[c + 3]), 0.0f);
    ((float4*)out)[idx] = v;
}

extern "C" void kernel_launch(void* const* d_in, const int* in_sizes, int n_in,
                              void* d_out, int out_size)
{
    const float* x  = (const float*)d_in[0];
    const float* w1 = (const float*)d_in[1];
    const float* g1 = (const float*)d_in[2];
    const float* b1 = (const float*)d_in[3];
    const float* w2 = (const float*)d_in[4];
    const float* g2 = (const float*)d_in[5];
    const float* b2 = (const float*)d_in[6];
    const int*   ei = (const int*)d_in[7];
    float* out = (float*)d_out;

    void *pS, *pT, *pdeg, *pP, *pQ, *pY, *ps1, *ps2;
    void *pXh, *pXl, *pSh, *pSl, *pZh, *pZl;
    void *pAth, *pAtl, *pBwth, *pBwtl, *pCwth, *pCwtl, *pw2h, *pw2l;
    cudaGetSymbolAddress(&pS,   g_S);
    cudaGetSymbolAddress(&pT,   g_T);
    cudaGetSymbolAddress(&pdeg, g_deg);
    cudaGetSymbolAddress(&pP,   g_P);
    cudaGetSymbolAddress(&pQ,   g_Q);
    cudaGetSymbolAddress(&pY,   g_Y);
    cudaGetSymbolAddress(&ps1,  g_stat1);
    cudaGetSymbolAddress(&ps2,  g_stat2);
    cudaGetSymbolAddress(&pXh,  g_Xh);  cudaGetSymbolAddress(&pXl, g_Xl);
    cudaGetSymbolAddress(&pSh,  g_Sh);  cudaGetSymbolAddress(&pSl, g_Sl);
    cudaGetSymbolAddress(&pZh,  g_Zh);  cudaGetSymbolAddress(&pZl, g_Zl);
    cudaGetSymbolAddress(&pAth,  g_At_h);  cudaGetSymbolAddress(&pAtl,  g_At_l);
    cudaGetSymbolAddress(&pBwth, g_Bwt_h); cudaGetSymbolAddress(&pBwtl, g_Bwt_l);
    cudaGetSymbolAddress(&pCwth, g_Cwt_h); cudaGetSymbolAddress(&pCwtl, g_Cwt_l);
    cudaGetSymbolAddress(&pw2h,  g_w2t_h); cudaGetSymbolAddress(&pw2l,  g_w2t_l);

    const int shb = (int)sizeof(SmemGemm);
    cudaFuncSetAttribute(gemm_bf16<128, 256, 0>, cudaFuncAttributeMaxDynamicSharedMemorySize, shb);
    cudaFuncSetAttribute(gemm_bf16<256, 256, 0>, cudaFuncAttributeMaxDynamicSharedMemorySize, shb);
    cudaFuncSetAttribute(gemm_bf16<128, 256, 1>, cudaFuncAttributeMaxDynamicSharedMemorySize, shb);
    cudaFuncSetAttribute(gemm_bf16<256, 128, 2>, cudaFuncAttributeMaxDynamicSharedMemorySize, shb);

    cudaMemsetAsync(pS,   0, sizeof(g_S));
    cudaMemsetAsync(pT,   0, sizeof(g_T));
    cudaMemsetAsync(pdeg, 0, sizeof(g_deg));
    cudaMemsetAsync(ps1,  0, sizeof(g_stat1));
    cudaMemsetAsync(ps2,  0, sizeof(g_stat2));

    prep_w<<<256, 256>>>(w1);
    prep_w2<<<128, 256>>>(w2);
    split_x<<<ROWSZ * CDIM / 4 / 256, 256>>>(x);
    edge_accum<<<(EDGES + 7) / 8, 256>>>(x, ei);
    build_Z<<<NPAD * CDIM / 256, 256>>>();

    // node GEMMs: P = S@Bw, Q = Z@Cw
    gemm_bf16<128, 256, 0><<<dim3(2, NPAD / 128), 256, shb>>>(
        (const __nv_bfloat16*)pSh, (const __nv_bfloat16*)pSl, nullptr,
        (const __nv_bfloat16*)pBwth, (const __nv_bfloat16*)pBwtl, (float*)pP, nullptr);
    gemm_bf16<256, 256, 0><<<dim3(2, NPAD / 128), 256, shb>>>(
        (const __nv_bfloat16*)pZh, (const __nv_bfloat16*)pZl, nullptr,
        (const __nv_bfloat16*)pCwth, (const __nv_bfloat16*)pCwtl, (float*)pQ, nullptr);

    // GEMM1: Y = x@A + P[other] + Q[node], stats1
    gemm_bf16<128, 256, 1><<<dim3(2, ROWSZ / 128), 256, shb>>>(
        (const __nv_bfloat16*)pXh, (const __nv_bfloat16*)pXl, nullptr,
        (const __nv_bfloat16*)pAth, (const __nv_bfloat16*)pAtl, (float*)pY, ei);
    finalize1<<<1, 256>>>(g1, b1);

    // GEMM2: d_out = relu(bn1(Y))@w2 (pre-BN2), stats2
    gemm_bf16<256, 128, 2><<<dim3(1, ROWSZ / 128), 256, shb>>>(
        nullptr, nullptr, (const float*)pY,
        (const __nv_bfloat16*)pw2h, (const __nv_bfloat16*)pw2l, out, nullptr);
    finalize2<<<1, 128>>>(g2, b2);

    bn2_relu<<<ROWSZ * 32 / 256, 256>>>(out);
}